// round 17
// baseline (speedup 1.0000x reference)
#include <cuda_runtime.h>
#include <cstdint>
#include <math.h>
#include <mma.h>

using namespace nvcuda;

#define B_SZ   16384
#define NROWS  2048
#define NCOLS  128
#define CTRL   1024
#define NH     134            // NCOLS + 6
#define EPSV   1e-16f

// ---------------- scratch (device globals) ---------------------------------
__device__ float g_k[B_SZ * NCOLS];      // controller key k  [B,128]
__device__ float g_prm[B_SZ * 6];        // beta, g, s0,s1,s2, gamma
__device__ float g_mnorm[NROWS];         // ||M_j|| (exact)
__device__ float g_m32[NROWS * NCOLS];   // M rounded to tf32  [j][k]
__device__ float g_mt32[NCOLS * NROWS];  // M^T rounded to tf32 [k][j]

__device__ __forceinline__ float softplusf(float x) {
    return (x > 20.f) ? x : log1pf(expf(x));
}
__device__ __forceinline__ float fast_exp2f(float y) {
    y = fminf(fmaxf(y, -125.f), 126.f);
    float r = y + 12582912.f;
    int   n = __float_as_int(r) - 0x4B400000;
    float f = y - (r - 12582912.f);
    float p = 1.54035304e-4f;
    p = fmaf(p, f, 1.33335581e-3f);
    p = fmaf(p, f, 9.61812911e-3f);
    p = fmaf(p, f, 5.55041087e-2f);
    p = fmaf(p, f, 2.40226507e-1f);
    p = fmaf(p, f, 6.93147183e-1f);
    p = fmaf(p, f, 1.0f);
    return __int_as_float(__float_as_int(p) + (n << 23));
}
__device__ __forceinline__ float fast_expf(float x) { return fast_exp2f(x * 1.442695041f); }
__device__ __forceinline__ float fast_log2f(float x) {
    int   ib = __float_as_int(x);
    int   e  = (ib - 0x3f2aaaab) & 0xff800000;
    float m  = __int_as_float(ib - e);
    float le = (float)(e >> 23);
    float f  = m - 1.0f;
    float s  = f * f;
    float r  = fmaf(0.230836749f, f, -0.279208571f);
    float t  = fmaf(0.331826031f, f, -0.498910338f);
    r = fmaf(r, s, t);
    r = fmaf(r, s, f);
    return fmaf(r, 1.442695041f, le);
}
__device__ __forceinline__ float fast_powf(float x, float g) {
    return fast_exp2f(g * fast_log2f(x));
}
__device__ __forceinline__ float to_tf32f(float x) {
    uint32_t r; asm("cvt.rna.tf32.f32 %0, %1;" : "=r"(r) : "f"(x));
    return __uint_as_float(r);
}

typedef wmma::fragment<wmma::matrix_a, 16, 16, 8, wmma::precision::tf32, wmma::row_major> FragA;
typedef wmma::fragment<wmma::matrix_b, 16, 16, 8, wmma::precision::tf32, wmma::col_major> FragBC;
typedef wmma::fragment<wmma::matrix_b, 16, 16, 8, wmma::precision::tf32, wmma::row_major> FragBR;
typedef wmma::fragment<wmma::accumulator, 16, 16, 8, float> FragC;

// ---------------- K0: M row norms (exact) + tf32 copies --------------------
__global__ void k0_mnorm(const float* __restrict__ M) {
    int row  = blockIdx.x * 8 + (threadIdx.x >> 5);
    int lane = threadIdx.x & 31;
    float4 v = ((const float4*)(M + (size_t)row * NCOLS))[lane];
    float s = v.x*v.x + v.y*v.y + v.z*v.z + v.w*v.w;
    #pragma unroll
    for (int o = 16; o > 0; o >>= 1) s += __shfl_xor_sync(0xffffffffu, s, o);
    if (lane == 0) g_mnorm[row] = sqrtf(s);
}
__global__ void k0_mrnd(const float* __restrict__ M) {
    int idx = blockIdx.x * 256 + threadIdx.x;
    g_m32[idx] = to_tf32f(M[idx]);
}
__global__ void k0_mt32(const float* __restrict__ M) {
    int idx = blockIdx.x * 256 + threadIdx.x;      // [k][j] order, j fastest
    int c = idx >> 11, j = idx & 2047;
    g_mt32[idx] = to_tf32f(__ldg(M + (size_t)j * NCOLS + c));
}

// ---------------- K1: h = x@W + b, BM=64, register prefetch ----------------
#define BM1 64
#define K1_AS    0        // [32][68] exact k-major (param path)
#define K1_AS32  2176     // [64][36] tf32
#define K1_BS32  4480     // [128][36] tf32
#define K1_STAGE 0        // [64][132] overlaps union post-mainloop
#define K1_PS    9088     // [32][6]
#define K1_HP    9280     // [2][64][6]
#define K1_SMEM  ((9280 + 768) * 4)

__global__ __launch_bounds__(256)
void k1_gemm(const float* __restrict__ x, const float* __restrict__ W,
             const float* __restrict__ bfc) {
    extern __shared__ float sm1f[];
    float* As    = sm1f + K1_AS;
    float* As32  = sm1f + K1_AS32;
    float* Bs32  = sm1f + K1_BS32;
    float* stage = sm1f + K1_STAGE;
    float* Ps    = sm1f + K1_PS;
    float* hp    = sm1f + K1_HP;

    int tid  = threadIdx.x;
    int wid  = tid >> 5;
    int wm   = wid >> 2, wn = wid & 3;
    int row0 = blockIdx.x * BM1;
    int mp   = tid & 63;
    int cg   = (tid >> 6) & 1;
    int kh   = tid >> 7;

    FragC acc[2][2];
    #pragma unroll
    for (int mi = 0; mi < 2; mi++)
        #pragma unroll
        for (int ni = 0; ni < 2; ni++) wmma::fill_fragment(acc[mi][ni], 0.0f);
    float acc3[3] = {0.f, 0.f, 0.f};

    // prefetch registers
    float4 xv[2];
    float  wv[16];
    float  pvv = 0.f;
    int xm[2], xc[2];
    #pragma unroll
    for (int u = 0; u < 2; u++) {
        int idx = tid + u * 256;
        xm[u] = idx >> 3; xc[u] = idx & 7;
    }
    // prefetch tile 0
    #pragma unroll
    for (int u = 0; u < 2; u++)
        xv[u] = *(const float4*)(x + (size_t)(row0 + xm[u]) * CTRL + xc[u] * 4);
    #pragma unroll
    for (int u = 0; u < 16; u++) {
        int id = tid + u * 256;
        wv[u] = W[(size_t)(id >> 7) * NH + (id & 127)];
    }
    if (tid < 192)
        pvv = W[(size_t)(tid / 6) * NH + 128 + (tid % 6)];

    for (int kt = 0; kt < CTRL / 32; kt++) {
        #pragma unroll
        for (int u = 0; u < 2; u++) {
            int m = xm[u], c4 = xc[u];
            float4 v = xv[u];
            As[(c4*4+0)*68 + m] = v.x; As[(c4*4+1)*68 + m] = v.y;
            As[(c4*4+2)*68 + m] = v.z; As[(c4*4+3)*68 + m] = v.w;
            float* d = As32 + m * 36 + c4 * 4;
            d[0] = to_tf32f(v.x); d[1] = to_tf32f(v.y);
            d[2] = to_tf32f(v.z); d[3] = to_tf32f(v.w);
        }
        #pragma unroll
        for (int u = 0; u < 16; u++) {
            int id = tid + u * 256;
            Bs32[(id & 127) * 36 + (id >> 7)] = to_tf32f(wv[u]);
        }
        if (tid < 192)
            Ps[tid] = pvv;
        __syncthreads();

        // prefetch next tile (overlaps MMA + param FMA below)
        if (kt + 1 < CTRL / 32) {
            int kb = (kt + 1) * 32;
            #pragma unroll
            for (int u = 0; u < 2; u++)
                xv[u] = *(const float4*)(x + (size_t)(row0 + xm[u]) * CTRL + kb + xc[u] * 4);
            #pragma unroll
            for (int u = 0; u < 16; u++) {
                int id = tid + u * 256;
                wv[u] = W[(size_t)(kb + (id >> 7)) * NH + (id & 127)];
            }
            if (tid < 192)
                pvv = W[(size_t)(kb + tid / 6) * NH + 128 + (tid % 6)];
        }

        #pragma unroll
        for (int ks = 0; ks < 4; ks++) {
            int k0 = ks * 8;
            FragA a[2];
            #pragma unroll
            for (int mi = 0; mi < 2; mi++)
                wmma::load_matrix_sync(a[mi], As32 + (wm*32 + mi*16) * 36 + k0, 36);
            #pragma unroll
            for (int ni = 0; ni < 2; ni++) {
                FragBC b;
                wmma::load_matrix_sync(b, Bs32 + (wn*32 + ni*16) * 36 + k0, 36);
                #pragma unroll
                for (int mi = 0; mi < 2; mi++)
                    wmma::mma_sync(acc[mi][ni], a[mi], b, acc[mi][ni]);
            }
        }
        #pragma unroll 8
        for (int kk = kh * 16; kk < kh * 16 + 16; kk++) {
            float xvv = As[kk*68 + mp];
            #pragma unroll
            for (int c = 0; c < 3; c++)
                acc3[c] = fmaf(xvv, Ps[kk*6 + cg*3 + c], acc3[c]);
        }
        __syncthreads();
    }

    #pragma unroll
    for (int mi = 0; mi < 2; mi++)
        #pragma unroll
        for (int ni = 0; ni < 2; ni++)
            wmma::store_matrix_sync(stage + (wm*32 + mi*16) * 132 + wn*32 + ni*16,
                                    acc[mi][ni], 132, wmma::mem_row_major);
    #pragma unroll
    for (int c = 0; c < 3; c++)
        hp[kh*384 + mp*6 + cg*3 + c] = acc3[c];
    __syncthreads();

    {
        int c4 = tid & 31;
        float4 bj = *(const float4*)(bfc + c4 * 4);
        #pragma unroll
        for (int u = 0; u < 8; u++) {
            int idx = tid + u * 256;
            int row = idx >> 5;
            float4 v = *(float4*)&stage[row * 132 + c4 * 4];
            v.x += bj.x; v.y += bj.y; v.z += bj.z; v.w += bj.w;
            *(float4*)(g_k + (size_t)(row0 + row) * NCOLS + c4 * 4) = v;
        }
    }
    if (tid < 64) {
        float h[6];
        #pragma unroll
        for (int c = 0; c < 6; c++)
            h[c] = hp[tid*6 + c] + hp[384 + tid*6 + c] + bfc[128 + c];
        float beta  = softplusf(h[0]);
        float g     = 1.f / (1.f + expf(-h[1]));
        float m3    = fmaxf(h[2], fmaxf(h[3], h[4]));
        float e0 = expf(h[2] - m3), e1 = expf(h[3] - m3), e2 = expf(h[4] - m3);
        float inv = 1.f / (e0 + e1 + e2);
        float gamma = 1.f + softplusf(h[5]);
        size_t gr = (size_t)(row0 + tid) * 6;
        g_prm[gr+0] = beta;  g_prm[gr+1] = g;
        g_prm[gr+2] = e0*inv; g_prm[gr+3] = e1*inv; g_prm[gr+4] = e2*inv;
        g_prm[gr+5] = gamma;
    }
}

// ---------------- K2: fused addressing + read, 1024 threads ----------------
#define RPB  16
#define K2T  1024
#define WSTR 2056     // wbuf row stride
#define KSTR 136      // ks row stride
#define SCRL 136
#define NKQ  4
#define KCH  32       // read-GEMM staged k-rows per buffer (double-buffered)
#define BSTL 132      // staging row stride
// smem floats: wbuf 16*2056 | ks 16*136 | scr(∪Bst×2) 4*16*136 | prm 128 | kn 16 | ips 16 | msh 2048
#define K2_SMEM_FLOATS (RPB*WSTR + RPB*KSTR + NKQ*RPB*SCRL + RPB*8 + RPB + RPB + 2048)
#define K2_SMEM_BYTES  (K2_SMEM_FLOATS * 4)

__global__ __launch_bounds__(K2T)
void k2_fused(const float* __restrict__ wprev, float* __restrict__ out) {
    extern __shared__ float smf[];
    float* wbuf = smf;                         // [16][2056]
    float* ks   = wbuf + RPB*WSTR;             // [16][136]
    float* scr  = ks + RPB*KSTR;               // [4][16][136]  (∪ Bst[2][32][132])
    float* prm  = scr + NKQ*RPB*SCRL;          // [16][8]
    float* kn   = prm + RPB*8;                 // [16]
    float* ips  = kn + RPB;                    // [16]
    float* msh  = ips + RPB;                   // [2048] 1/||M_j||

    int tid  = threadIdx.x;
    int lane = tid & 31;
    int wid  = tid >> 5;                       // 0..31
    int row0 = blockIdx.x * RPB;

    if (tid < 512) {
        int r = tid >> 5;
        float4 v = *(const float4*)(g_k + (size_t)(row0 + r) * NCOLS + lane*4);
        *(float4*)&ks[r*KSTR + lane*4] = v;
    }
    if (tid < RPB*6) {
        int r = tid / 6, c = tid % 6;
        prm[r*8 + c] = g_prm[(size_t)(row0 + r) * 6 + c];
    }
    for (int i = tid; i < NROWS; i += K2T)
        msh[i] = 1.0f / g_mnorm[i];
    __syncthreads();

    if (wid < 16) {
        float s = 0.f;
        #pragma unroll
        for (int u = 0; u < 4; u++) {
            float v = ks[wid*KSTR + lane + 32*u];
            s += v * v;
        }
        #pragma unroll
        for (int o = 16; o > 0; o >>= 1) s += __shfl_xor_sync(0xffffffffu, s, o);
        if (lane == 0) kn[wid] = sqrtf(s);
    }
    __syncthreads();

    for (int i = tid; i < RPB*NCOLS; i += K2T) {
        int r = i >> 7, c = i & 127;
        ks[r*KSTR + c] = to_tf32f(ks[r*KSTR + c]);
    }
    __syncthreads();

    // ---- sim GEMM: B = M^T (row-major frags, 64B segments) ----------------
    {
        FragC acc[4];
        #pragma unroll
        for (int i = 0; i < 4; i++) wmma::fill_fragment(acc[i], 0.0f);
        #pragma unroll
        for (int kk = 0; kk < 16; kk++) {
            FragA a;
            wmma::load_matrix_sync(a, ks + kk*8, KSTR);
            #pragma unroll
            for (int i = 0; i < 4; i++) {
                int j0 = (wid * 4 + i) * 16;
                FragBR b;
                wmma::load_matrix_sync(b, g_mt32 + (size_t)(kk*8) * NROWS + j0, NROWS);
                wmma::mma_sync(acc[i], a, b, acc[i]);
            }
        }
        #pragma unroll
        for (int i = 0; i < 4; i++) {
            int j0 = (wid * 4 + i) * 16;
            wmma::store_matrix_sync(wbuf + j0, acc[i], WSTR, wmma::mem_row_major);
        }
    }
    __syncthreads();

    // ---- pointwise (warps 0..15, one row each; scale folded) --------------
    if (wid < 16) {
        int r = wid;
        float* wr = wbuf + r*WSTR;
        float rs = prm[r*8+0] / kn[r];
        float g  = prm[r*8+1], s0 = prm[r*8+2], s1 = prm[r*8+3];
        float s2 = prm[r*8+4], gm = prm[r*8+5];

        float mx = -1e30f;
        for (int u = 0; u < 64; u++) {
            int idx = lane + 32*u;
            mx = fmaxf(mx, wr[idx] * rs * msh[idx]);
        }
        #pragma unroll
        for (int o = 16; o > 0; o >>= 1) mx = fmaxf(mx, __shfl_xor_sync(0xffffffffu, mx, o));

        float sum = 0.f;
        for (int u = 0; u < 64; u++) {
            int idx = lane + 32*u;
            float e = fast_expf(wr[idx] * rs * msh[idx] - mx);
            wr[idx] = e;
            sum += e;
        }
        #pragma unroll
        for (int o = 16; o > 0; o >>= 1) sum += __shfl_xor_sync(0xffffffffu, sum, o);

        float gc = g / sum, og = 1.f - g;
        const float* wp = wprev + (size_t)(row0 + r) * NROWS;
        for (int u = 0; u < 64; u++) {
            int idx = lane + 32*u;
            wr[idx] = gc * wr[idx] + og * __ldg(wp + idx);
        }
        __syncwarp();

        float w0    = wr[0];
        float carry = wr[NROWS - 1];
        float psum  = 0.f;
        for (int ch = 0; ch < 64; ch++) {
            int j = ch*32 + lane;
            float c0  = wr[j];
            float lft = (lane == 0)      ? carry : wr[j-1];
            float rgt = (j == NROWS - 1) ? w0    : wr[j+1];
            float t = s0*lft + s1*c0 + s2*rgt + EPSV;
            float p = fast_powf(t, gm);
            __syncwarp();
            wr[j] = to_tf32f(p);
            carry = __shfl_sync(0xffffffffu, c0, 31);
            psum += p;
            __syncwarp();
        }
        #pragma unroll
        for (int o = 16; o > 0; o >>= 1) psum += __shfl_xor_sync(0xffffffffu, psum, o);
        if (lane == 0) ips[r] = 1.f / psum;
    }
    __syncthreads();

    // ---- read GEMM: out_blk = w @ M, double-buffered staged M chunks ------
    {
        int n0 = (wid & 7) * 16;
        int kq = wid >> 3;                     // 0..3
        int sr = tid >> 5, sc = tid & 31;      // staging: row 0..31, col4 0..31
        FragC acc;
        wmma::fill_fragment(acc, 0.0f);

        // stage chunk 0 into buffer 0
        {
            float4 v = *(const float4*)(g_m32 + (size_t)sr * NCOLS + sc * 4);
            *(float4*)&scr[sr*BSTL + sc*4] = v;
        }
        __syncthreads();

        for (int oc = 0; oc < NROWS / KCH; oc++) {       // 64 chunks
            float* cur = scr + (oc & 1) * (KCH * BSTL);
            // prefetch next chunk into the other buffer (overlaps MMA)
            if (oc + 1 < NROWS / KCH) {
                float* nxt = scr + ((oc + 1) & 1) * (KCH * BSTL);
                float4 v = *(const float4*)(g_m32 +
                    (size_t)((oc + 1) * KCH + sr) * NCOLS + sc * 4);
                *(float4*)&nxt[sr*BSTL + sc*4] = v;
            }
            // MMA on current chunk: warp kq handles local k-rows [kq*8, kq*8+8)
            {
                int kr = kq * 8;
                FragA a;
                FragBR b;
                wmma::load_matrix_sync(a, wbuf + (oc*KCH + kr), WSTR);
                wmma::load_matrix_sync(b, cur + kr*BSTL + n0, BSTL);
                wmma::mma_sync(acc, a, b, acc);
            }
            __syncthreads();
        }
        // scr overlaps Bst buffers; all reads complete (sync above)
        wmma::store_matrix_sync(scr + kq * RPB * SCRL + n0, acc, SCRL,
                                wmma::mem_row_major);
    }
    __syncthreads();
    #pragma unroll
    for (int u = 0; u < 2; u++) {
        int idx = tid + u * K2T;
        int r = idx >> 7, c = idx & 127;
        float v = scr[r*SCRL + c] + scr[RPB*SCRL + r*SCRL + c]
                + scr[2*RPB*SCRL + r*SCRL + c] + scr[3*RPB*SCRL + r*SCRL + c];
        out[(size_t)(row0 + r) * NCOLS + c] = v * ips[r];
    }
}

// ---------------- launch ----------------------------------------------------
extern "C" void kernel_launch(void* const* d_in, const int* in_sizes, int n_in,
                              void* d_out, int out_size) {
    const float *x = 0, *W = 0, *b = 0, *M = 0, *wprev = 0;
    for (int i = 0; i < n_in; i++) {
        switch (in_sizes[i]) {
            case B_SZ * CTRL:   x     = (const float*)d_in[i]; break;
            case CTRL * NH:     W     = (const float*)d_in[i]; break;
            case NH:            b     = (const float*)d_in[i]; break;
            case NROWS * NCOLS: M     = (const float*)d_in[i]; break;
            case B_SZ * NROWS:  wprev = (const float*)d_in[i]; break;
        }
    }
    float* out = (float*)d_out;

    cudaFuncSetAttribute(k1_gemm, cudaFuncAttributeMaxDynamicSharedMemorySize, K1_SMEM);
    cudaFuncSetAttribute(k2_fused, cudaFuncAttributeMaxDynamicSharedMemorySize,
                         K2_SMEM_BYTES);

    k0_mnorm<<<NROWS/8, 256>>>(M);
    k0_mrnd <<<(NROWS*NCOLS)/256, 256>>>(M);
    k0_mt32 <<<(NROWS*NCOLS)/256, 256>>>(M);
    k1_gemm <<<B_SZ/BM1, 256, K1_SMEM>>>(x, W, b);
    k2_fused<<<B_SZ/RPB, K2T, K2_SMEM_BYTES>>>(wprev, out);
}